// round 14
// baseline (speedup 1.0000x reference)
#include <cuda_runtime.h>
#include <math.h>
#include <stdint.h>

#define HDIM 1024
#define IDIM 4096
#define NEXP 8
#define NTOK 4096
#define NSLOT 8192
#define TM 128
#define PAD_MAX 9216
#define TILE_MAX 72
#define RB 48              // smem row bytes: 32 data + 16 pad

// ---------------- device scratch (static, zero-init) ----------------
__device__ int   g_perm[PAD_MAX];
__device__ int   g_tile_expert[TILE_MAX];
__device__ int   g_tile_row0[TILE_MAX];
__device__ __align__(16) char g_xqh[(size_t)NTOK * HDIM], g_xql[(size_t)NTOK * HDIM];
__device__ float g_sx[NTOK];
__device__ __align__(16) char g_gqh[(size_t)NEXP * IDIM * HDIM], g_gql[(size_t)NEXP * IDIM * HDIM];
__device__ float g_sg[NEXP * IDIM];
__device__ __align__(16) char g_uqh[(size_t)NEXP * IDIM * HDIM], g_uql[(size_t)NEXP * IDIM * HDIM];
__device__ float g_su[NEXP * IDIM];
__device__ __align__(16) char g_dqh[(size_t)NEXP * HDIM * IDIM], g_dql[(size_t)NEXP * HDIM * IDIM];
__device__ float g_sd[NEXP * HDIM];
__device__ float g_act[(size_t)PAD_MAX * IDIM];
__device__ __align__(16) char g_aqh[(size_t)PAD_MAX * IDIM], g_aql[(size_t)PAD_MAX * IDIM];
__device__ float g_sa[PAD_MAX];
__device__ float g_y[(size_t)NSLOT * HDIM];

// ---------------- helpers ----------------
__device__ __forceinline__ uint32_t smem_to_u32(const void* p) {
    uint32_t a;
    asm("{ .reg .u64 t; cvta.to.shared.u64 t, %1; cvt.u32.u64 %0, t; }" : "=r"(a) : "l"(p));
    return a;
}
__device__ __forceinline__ void ldsm4(uint32_t* r, uint32_t addr) {
    asm volatile("ldmatrix.sync.aligned.m8n8.x4.shared.b16 {%0,%1,%2,%3}, [%4];"
                 : "=r"(r[0]), "=r"(r[1]), "=r"(r[2]), "=r"(r[3]) : "r"(addr));
}
__device__ __forceinline__ void mma_s8(int* c, const uint32_t* a, uint32_t b0, uint32_t b1) {
    asm volatile(
        "mma.sync.aligned.m16n8k32.row.col.s32.s8.s8.s32 "
        "{%0,%1,%2,%3}, {%4,%5,%6,%7}, {%8,%9}, {%0,%1,%2,%3};"
        : "+r"(c[0]), "+r"(c[1]), "+r"(c[2]), "+r"(c[3])
        : "r"(a[0]), "r"(a[1]), "r"(a[2]), "r"(a[3]), "r"(b0), "r"(b1));
}
// ldmatrix x4 on b16-view of s8 tile (rows x 32B, stride RB)
__device__ __forceinline__ uint32_t i8addr(uint32_t base, int row, int lane) {
    return base + (uint32_t)((row + (lane & 15)) * RB + ((lane >> 4) & 1) * 16);
}
__device__ __forceinline__ float silu_mul(float g, float u) {
    return g * u / (1.0f + expf(-g));
}

// ---------------- per-row 2-digit int8 quantization ----------------
__global__ __launch_bounds__(256)
void quant_rows(const float* __restrict__ xsrc, int which, int ncols) {
    int row = blockIdx.x, tid = threadIdx.x;
    const float* src; char *qh, *ql; float* sc;
    switch (which) {
        case 0:  src = xsrc;  qh = g_xqh; ql = g_xql; sc = g_sx; break;
        case 1:  src = xsrc;  qh = g_gqh; ql = g_gql; sc = g_sg; break;
        case 2:  src = xsrc;  qh = g_uqh; ql = g_uql; sc = g_su; break;
        case 3:  src = xsrc;  qh = g_dqh; ql = g_dql; sc = g_sd; break;
        default: src = g_act; qh = g_aqh; ql = g_aql; sc = g_sa; break;
    }
    const float* rp = src + (size_t)row * ncols;
    __shared__ float red[256];
    float m = 0.f;
    for (int c = tid * 4; c < ncols; c += 1024) {
        float4 v = *(const float4*)(rp + c);
        m = fmaxf(m, fmaxf(fmaxf(fabsf(v.x), fabsf(v.y)), fmaxf(fabsf(v.z), fabsf(v.w))));
    }
    red[tid] = m;
    __syncthreads();
    for (int s = 128; s > 0; s >>= 1) {
        if (tid < s) red[tid] = fmaxf(red[tid], red[tid + s]);
        __syncthreads();
    }
    float scale = fmaxf(red[0], 1e-20f) * (1.f / 127.f);
    if (tid == 0) sc[row] = scale;
    float inv = 1.f / scale;
    for (int c = tid * 4; c < ncols; c += 1024) {
        float4 v = *(const float4*)(rp + c);
        float t0 = v.x * inv, t1 = v.y * inv, t2 = v.z * inv, t3 = v.w * inv;
        float h0 = rintf(t0), h1 = rintf(t1), h2 = rintf(t2), h3 = rintf(t3);
        *(char4*)(qh + (size_t)row * ncols + c) =
            make_char4((char)(int)h0, (char)(int)h1, (char)(int)h2, (char)(int)h3);
        *(char4*)(ql + (size_t)row * ncols + c) =
            make_char4((char)(int)rintf((t0 - h0) * 128.f), (char)(int)rintf((t1 - h1) * 128.f),
                       (char)(int)rintf((t2 - h2) * 128.f), (char)(int)rintf((t3 - h3) * 128.f));
    }
}

// ---------------- routing ----------------
__global__ void route_kernel(const int* __restrict__ ei) {
    __shared__ int cnt[NEXP];
    __shared__ int cur[NEXP];
    int tid = threadIdx.x;
    if (tid < NEXP) cnt[tid] = 0;
    __syncthreads();
    for (int s = tid; s < NSLOT; s += blockDim.x) atomicAdd(&cnt[ei[s]], 1);
    __syncthreads();
    if (tid == 0) {
        int base = 0, tile = 0;
        for (int e = 0; e < NEXP; e++) {
            cur[e] = base;
            int nt = (cnt[e] + TM - 1) / TM;
            for (int j = 0; j < nt; j++) { g_tile_expert[tile] = e; g_tile_row0[tile] = base + j * TM; tile++; }
            base += nt * TM;
        }
        for (; tile < TILE_MAX; tile++) g_tile_expert[tile] = -1;
    }
    __syncthreads();
    for (int r = tid; r < PAD_MAX; r += blockDim.x) g_perm[r] = -1;
    __syncthreads();
    for (int s = tid; s < NSLOT; s += blockDim.x) {
        int e = ei[s];
        int pos = atomicAdd(&cur[e], 1);
        g_perm[pos] = s;
    }
}

// ---------------- GEMM1 (s8): act = silu(x.gT)*(x.uT), CTA 128x32 ----------------
__global__ __launch_bounds__(256, 2)
void gemm1_i8() {
    int e = g_tile_expert[blockIdx.y];
    if (e < 0) return;
    int row0 = g_tile_row0[blockIdx.y];
    int i0 = blockIdx.x * 32;

    __shared__ __align__(16) char sXH[TM * RB], sXL[TM * RB];
    __shared__ __align__(16) char sGH[32 * RB], sGL[32 * RB], sUH[32 * RB], sUL[32 * RB];
    __shared__ float ssx[TM], ssg[32], ssu[32];
    __shared__ int toks[TM];

    int tid = threadIdx.x, lane = tid & 31, wid = tid >> 5;
    int mw = (wid >> 1) * 32, nw = (wid & 1) * 16;

    if (tid < TM) {
        int p = g_perm[row0 + tid];
        int tk = (p >= 0) ? (p >> 1) : -1;
        toks[tid] = tk;
        ssx[tid] = (tk >= 0) ? g_sx[tk] : 0.f;
    }
    if (tid < 32) {
        ssg[tid] = g_sg[e * IDIM + i0 + tid];
        ssu[tid] = g_su[e * IDIM + i0 + tid];
    }
    __syncthreads();

    int xr = tid >> 1, xh_ = tid & 1;
    int xtok = toks[xr];
    const char* xsh = (xtok >= 0) ? (g_xqh + (size_t)xtok * HDIM + xh_ * 16) : (const char*)0;
    const char* xsl = (xtok >= 0) ? (g_xql + (size_t)xtok * HDIM + xh_ * 16) : (const char*)0;
    char* xdh = sXH + xr * RB + xh_ * 16;
    char* xdl = sXL + xr * RB + xh_ * 16;

    int warr = tid >> 6, wr = (tid >> 1) & 31, wh_ = tid & 1;
    const char* ws0;
    char* wd0;
    switch (warr) {
        case 0:  ws0 = g_gqh; wd0 = sGH; break;
        case 1:  ws0 = g_gql; wd0 = sGL; break;
        case 2:  ws0 = g_uqh; wd0 = sUH; break;
        default: ws0 = g_uql; wd0 = sUL; break;
    }
    const char* wsrc = ws0 + (size_t)(e * IDIM + i0 + wr) * HDIM + wh_ * 16;
    char* wdst = wd0 + wr * RB + wh_ * 16;

    uint32_t bXH = smem_to_u32(sXH), bXL = smem_to_u32(sXL);
    uint32_t bGH = smem_to_u32(sGH), bGL = smem_to_u32(sGL);
    uint32_t bUH = smem_to_u32(sUH), bUL = smem_to_u32(sUL);

    int ag[2][2][4] = {}, bg[2][2][4] = {}, au[2][2][4] = {}, bu[2][2][4] = {};

    for (int cb = 0; cb < HDIM; cb += 32) {
        uint4 vh = xsh ? *(const uint4*)(xsh + cb) : make_uint4(0, 0, 0, 0);
        uint4 vl = xsl ? *(const uint4*)(xsl + cb) : make_uint4(0, 0, 0, 0);
        *(uint4*)xdh = vh;
        *(uint4*)xdl = vl;
        *(uint4*)wdst = *(const uint4*)(wsrc + cb);
        __syncthreads();

        uint32_t fgh[4], fgl[4], fuh[4], ful[4];
        ldsm4(fgh, i8addr(bGH, nw, lane));
        ldsm4(fgl, i8addr(bGL, nw, lane));
        ldsm4(fuh, i8addr(bUH, nw, lane));
        ldsm4(ful, i8addr(bUL, nw, lane));
#pragma unroll
        for (int mf = 0; mf < 2; mf++) {
            uint32_t axh[4], axl[4];
            ldsm4(axh, i8addr(bXH, mw + mf * 16, lane));
            ldsm4(axl, i8addr(bXL, mw + mf * 16, lane));
#pragma unroll
            for (int nf = 0; nf < 2; nf++) {
                mma_s8(ag[mf][nf], axh, fgh[nf], fgh[nf + 2]);
                mma_s8(bg[mf][nf], axh, fgl[nf], fgl[nf + 2]);
                mma_s8(bg[mf][nf], axl, fgh[nf], fgh[nf + 2]);
                mma_s8(au[mf][nf], axh, fuh[nf], fuh[nf + 2]);
                mma_s8(bu[mf][nf], axh, ful[nf], ful[nf + 2]);
                mma_s8(bu[mf][nf], axl, fuh[nf], fuh[nf + 2]);
            }
        }
        __syncthreads();
    }

#pragma unroll
    for (int mf = 0; mf < 2; mf++) {
#pragma unroll
        for (int nf = 0; nf < 2; nf++) {
            int mb = mw + mf * 16 + (lane >> 2);
            int nb = nw + nf * 8 + ((lane & 3) << 1);
#pragma unroll
            for (int h = 0; h < 2; h++) {
                int m = mb + h * 8;
                float sx = ssx[m];
                float g0 = sx * ssg[nb]     * ((float)ag[mf][nf][h * 2]     + (float)bg[mf][nf][h * 2]     * 0.0078125f);
                float g1 = sx * ssg[nb + 1] * ((float)ag[mf][nf][h * 2 + 1] + (float)bg[mf][nf][h * 2 + 1] * 0.0078125f);
                float u0 = sx * ssu[nb]     * ((float)au[mf][nf][h * 2]     + (float)bu[mf][nf][h * 2]     * 0.0078125f);
                float u1 = sx * ssu[nb + 1] * ((float)au[mf][nf][h * 2 + 1] + (float)bu[mf][nf][h * 2 + 1] * 0.0078125f);
                float2 o;
                o.x = silu_mul(g0, u0);
                o.y = silu_mul(g1, u1);
                *(float2*)(g_act + (size_t)(row0 + m) * IDIM + i0 + nb) = o;
            }
        }
    }
}

// ---------------- GEMM2 (s8): y = ew*(act.dT), CTA 128x64 ----------------
__global__ __launch_bounds__(256, 2)
void gemm2_i8(const float* __restrict__ ew) {
    int e = g_tile_expert[blockIdx.y];
    if (e < 0) return;
    int row0 = g_tile_row0[blockIdx.y];
    int hb = blockIdx.x * 64;

    __shared__ __align__(16) char sAH[TM * RB], sAL[TM * RB];
    __shared__ __align__(16) char sWH[64 * RB], sWL[64 * RB];
    __shared__ float ssa[TM], ssd[64];
    __shared__ int   slots[TM];
    __shared__ float swt[TM];

    int tid = threadIdx.x, lane = tid & 31, wid = tid >> 5;
    int mw = (wid >> 2) * 64, nw = (wid & 3) * 16;

    if (tid < TM) {
        int p = g_perm[row0 + tid];
        slots[tid] = p;
        swt[tid] = (p >= 0) ? ew[p] : 0.f;
        ssa[tid] = g_sa[row0 + tid];
    }
    if (tid < 64) ssd[tid] = g_sd[e * HDIM + hb + tid];
    __syncthreads();

    int ar = tid >> 1, ah_ = tid & 1;
    const char* ash = g_aqh + (size_t)(row0 + ar) * IDIM + ah_ * 16;
    const char* asl = g_aql + (size_t)(row0 + ar) * IDIM + ah_ * 16;
    char* adh = sAH + ar * RB + ah_ * 16;
    char* adl = sAL + ar * RB + ah_ * 16;

    int darr = tid >> 7, dr = (tid >> 1) & 63, dh_ = tid & 1;
    const char* wsrc = (darr ? g_dql : g_dqh) + (size_t)(e * HDIM + hb + dr) * IDIM + dh_ * 16;
    char* wdst = (darr ? sWL : sWH) + dr * RB + dh_ * 16;

    uint32_t bAH = smem_to_u32(sAH), bAL = smem_to_u32(sAL);
    uint32_t bWH = smem_to_u32(sWH), bWL = smem_to_u32(sWL);

    int aA[4][2][4] = {}, aB[4][2][4] = {};

    for (int cb = 0; cb < IDIM; cb += 32) {
        *(uint4*)adh = *(const uint4*)(ash + cb);
        *(uint4*)adl = *(const uint4*)(asl + cb);
        *(uint4*)wdst = *(const uint4*)(wsrc + cb);
        __syncthreads();

        uint32_t fwh[4], fwl[4];
        ldsm4(fwh, i8addr(bWH, nw, lane));
        ldsm4(fwl, i8addr(bWL, nw, lane));
#pragma unroll
        for (int mf = 0; mf < 4; mf++) {
            uint32_t axh[4], axl[4];
            ldsm4(axh, i8addr(bAH, mw + mf * 16, lane));
            ldsm4(axl, i8addr(bAL, mw + mf * 16, lane));
#pragma unroll
            for (int nf = 0; nf < 2; nf++) {
                mma_s8(aA[mf][nf], axh, fwh[nf], fwh[nf + 2]);
                mma_s8(aB[mf][nf], axh, fwl[nf], fwl[nf + 2]);
                mma_s8(aB[mf][nf], axl, fwh[nf], fwh[nf + 2]);
            }
        }
        __syncthreads();
    }

#pragma unroll
    for (int mf = 0; mf < 4; mf++) {
#pragma unroll
        for (int nf = 0; nf < 2; nf++) {
            int mb = mw + mf * 16 + (lane >> 2);
            int nb = nw + nf * 8 + ((lane & 3) << 1);
#pragma unroll
            for (int h = 0; h < 2; h++) {
                int m = mb + h * 8;
                int p = slots[m];
                if (p >= 0) {
                    float s = swt[m] * ssa[m];
                    float2 o;
                    o.x = s * ssd[nb]     * ((float)aA[mf][nf][h * 2]     + (float)aB[mf][nf][h * 2]     * 0.0078125f);
                    o.y = s * ssd[nb + 1] * ((float)aA[mf][nf][h * 2 + 1] + (float)aB[mf][nf][h * 2 + 1] * 0.0078125f);
                    *(float2*)(g_y + (size_t)p * HDIM + hb + nb) = o;
                }
            }
        }
    }
}

// ---------------- combine ----------------
__global__ void combine_kernel(float* __restrict__ out) {
    const int HQ = HDIM / 4;
    int i = blockIdx.x * blockDim.x + threadIdx.x;
    if (i >= NTOK * HQ) return;
    int t = i / HQ, hq = i - t * HQ;
    const float4* y4 = (const float4*)g_y;
    float4 a = y4[(size_t)(2 * t) * HQ + hq];
    float4 b = y4[(size_t)(2 * t + 1) * HQ + hq];
    float4 o;
    o.x = a.x + b.x; o.y = a.y + b.y; o.z = a.z + b.z; o.w = a.w + b.w;
    ((float4*)out)[(size_t)t * HQ + hq] = o;
}

extern "C" void kernel_launch(void* const* d_in, const int* in_sizes, int n_in,
                              void* d_out, int out_size) {
    const float* x    = (const float*)d_in[0];
    const int*   ei   = (const int*)d_in[1];
    const float* ew   = (const float*)d_in[2];
    const float* gate = (const float*)d_in[3];
    const float* up   = (const float*)d_in[4];
    const float* down = (const float*)d_in[5];
    float* out = (float*)d_out;

    route_kernel<<<1, 256>>>(ei);
    quant_rows<<<NTOK, 256>>>(x, 0, HDIM);
    quant_rows<<<NEXP * IDIM, 256>>>(gate, 1, HDIM);
    quant_rows<<<NEXP * IDIM, 256>>>(up, 2, HDIM);
    quant_rows<<<NEXP * HDIM, 256>>>(down, 3, IDIM);

    gemm1_i8<<<dim3(IDIM / 32, TILE_MAX), 256>>>();
    quant_rows<<<PAD_MAX, 256>>>(x, 4, IDIM);
    gemm2_i8<<<dim3(HDIM / 64, TILE_MAX), 256>>>(ew);
    combine_kernel<<<(NTOK * (HDIM / 4) + 255) / 256, 256>>>(out);
}

// round 15
// speedup vs baseline: 2.5191x; 2.5191x over previous
#include <cuda_runtime.h>
#include <cuda_fp16.h>
#include <math.h>
#include <stdint.h>

// ---------------- problem constants ----------------
#define HDIM 1024
#define IDIM 4096
#define NEXP 8
#define NTOK 4096          // B*S
#define NSLOT 8192         // NTOK*TOPK
#define TM 128             // CTA M tile
#define TN 64              // CTA N tile
#define KC 32              // K elems per chunk
#define NCH1 (HDIM / KC)   // 32
#define NCH2 (IDIM / KC)   // 128
#define PAD_MAX 9216
#define TILE_MAX 72
#define STRD 40            // smem row stride in elems (32 + 8 pad) -> 80B rows

// ---------------- device scratch (static, no allocs) ----------------
__device__ int   g_perm[PAD_MAX];
__device__ int   g_tile_expert[TILE_MAX];
__device__ int   g_tile_row0[TILE_MAX];
// act stored pre-split as fp16 hi/lo, row-major [PAD_MAX][IDIM]
__device__ uint4 g_act_hi[(size_t)PAD_MAX * IDIM / 8];
__device__ uint4 g_act_lo[(size_t)PAD_MAX * IDIM / 8];
__device__ float g_y[(size_t)NSLOT * HDIM];

// ---------------- helpers ----------------
__device__ __forceinline__ uint32_t smem_to_u32(const void* p) {
    uint32_t a;
    asm("{ .reg .u64 t; cvta.to.shared.u64 t, %1; cvt.u32.u64 %0, t; }" : "=r"(a) : "l"(p));
    return a;
}
__device__ __forceinline__ void ldsm4(uint32_t* r, uint32_t addr) {
    asm volatile("ldmatrix.sync.aligned.m8n8.x4.shared.b16 {%0,%1,%2,%3}, [%4];"
                 : "=r"(r[0]), "=r"(r[1]), "=r"(r[2]), "=r"(r[3]) : "r"(addr));
}
__device__ __forceinline__ void mmaf16(float* c, const uint32_t* a, uint32_t b0, uint32_t b1) {
    asm volatile(
        "mma.sync.aligned.m16n8k16.row.col.f32.f16.f16.f32 "
        "{%0,%1,%2,%3}, {%4,%5,%6,%7}, {%8,%9}, {%0,%1,%2,%3};"
        : "+f"(c[0]), "+f"(c[1]), "+f"(c[2]), "+f"(c[3])
        : "r"(a[0]), "r"(a[1]), "r"(a[2]), "r"(a[3]), "r"(b0), "r"(b1));
}
// ldmatrix x4 address for a 16x16 block at (row, k) in a [.][STRD] f16 tile
__device__ __forceinline__ uint32_t lds_addr(uint32_t base, int row, int k, int lane) {
    int r = row + (lane & 15);
    int kk = k + ((lane >> 4) << 3);
    return base + (uint32_t)(r * (STRD * 2) + kk * 2);
}
__device__ __forceinline__ float silu_mul(float g, float u) {
    return g * u / (1.0f + expf(-g));
}
// split 8 fp32 into fp16 hi + fp16 residual (a ~= hi + lo, ~22 bits)
__device__ __forceinline__ void split8h(float4 v0, float4 v1, void* ph, void* pl) {
    float f[8] = {v0.x, v0.y, v0.z, v0.w, v1.x, v1.y, v1.z, v1.w};
    union { __half b[8]; uint4 u; } H, L;
#pragma unroll
    for (int j = 0; j < 8; j++) {
        __half h = __float2half(f[j]);
        H.b[j] = h;
        L.b[j] = __float2half(f[j] - __half2float(h));
    }
    *(uint4*)ph = H.u;
    *(uint4*)pl = L.u;
}
// convert 8 fp32 to fp16 (single digit, weights)
__device__ __forceinline__ void cvt8h(float4 v0, float4 v1, void* ph) {
    float f[8] = {v0.x, v0.y, v0.z, v0.w, v1.x, v1.y, v1.z, v1.w};
    union { __half b[8]; uint4 u; } H;
#pragma unroll
    for (int j = 0; j < 8; j++) H.b[j] = __float2half(f[j]);
    *(uint4*)ph = H.u;
}

// ---------------- routing (output-order invariant) ----------------
__global__ void route_kernel(const int* __restrict__ ei) {
    __shared__ int cnt[NEXP];
    __shared__ int cur[NEXP];
    int tid = threadIdx.x;
    if (tid < NEXP) cnt[tid] = 0;
    __syncthreads();
    for (int s = tid; s < NSLOT; s += blockDim.x) atomicAdd(&cnt[ei[s]], 1);
    __syncthreads();
    if (tid == 0) {
        int base = 0, tile = 0;
        for (int e = 0; e < NEXP; e++) {
            cur[e] = base;
            int nt = (cnt[e] + TM - 1) / TM;
            for (int j = 0; j < nt; j++) { g_tile_expert[tile] = e; g_tile_row0[tile] = base + j * TM; tile++; }
            base += nt * TM;
        }
        for (; tile < TILE_MAX; tile++) g_tile_expert[tile] = -1;
    }
    __syncthreads();
    for (int r = tid; r < PAD_MAX; r += blockDim.x) g_perm[r] = -1;
    __syncthreads();
    for (int s = tid; s < NSLOT; s += blockDim.x) {
        int e = ei[s];
        int pos = atomicAdd(&cur[e], 1);
        g_perm[pos] = s;
    }
}

// ---------------- GEMM1: act = silu(x.gateT) * (x.upT) ----------------
// x split 2-digit fp16; gate/up single-digit fp16 (weight-lo tiles eliminated).
__global__ __launch_bounds__(256, 2)
void gemm1_mma(const float* __restrict__ x,
               const float* __restrict__ gate,
               const float* __restrict__ up) {
    int e = g_tile_expert[blockIdx.y];
    if (e < 0) return;
    int row0 = g_tile_row0[blockIdx.y];
    int i0 = blockIdx.x * TN;

    __shared__ __align__(16) __half sXH[TM * STRD], sXL[TM * STRD];
    __shared__ __align__(16) __half sGH[TN * STRD], sUH[TN * STRD];
    __shared__ int toks[TM];

    int tid = threadIdx.x;
    int lane = tid & 31, wid = tid >> 5;
    int mw = (wid >> 2) * 64;      // warp M offset
    int nw = (wid & 3) * 16;       // warp N offset

    if (tid < TM) {
        int p = g_perm[row0 + tid];
        toks[tid] = (p >= 0) ? (p >> 1) : -1;
    }
    __syncthreads();

    uint32_t bXH = smem_to_u32(sXH), bXL = smem_to_u32(sXL);
    uint32_t bGH = smem_to_u32(sGH), bUH = smem_to_u32(sUH);

    // weight-staging task for this thread (fixed across chunks)
    int wr = tid >> 2, wk0 = (tid & 3) << 3;
    const float* gptr = gate + ((size_t)e * IDIM + i0 + wr) * HDIM + wk0;
    const float* uptr = up   + ((size_t)e * IDIM + i0 + wr) * HDIM + wk0;
    int woff = wr * STRD + wk0;

    float cg[4][2][4], cu[4][2][4];
#pragma unroll
    for (int mf = 0; mf < 4; mf++)
#pragma unroll
        for (int nf = 0; nf < 2; nf++)
#pragma unroll
            for (int q = 0; q < 4; q++) { cg[mf][nf][q] = 0.f; cu[mf][nf][q] = 0.f; }

    // prologue: prefetch weights for chunk 0
    float4 pg0 = *(const float4*)(gptr);
    float4 pg1 = *(const float4*)(gptr + 4);
    float4 pu0 = *(const float4*)(uptr);
    float4 pu1 = *(const float4*)(uptr + 4);

    for (int ch = 0; ch < NCH1; ch++) {
        int h0 = ch * KC;
        // stage x (gathered rows, 2-digit split): 512 tasks of 8 elems
#pragma unroll
        for (int l = 0; l < 2; l++) {
            int s = tid + l * 256;
            int row = s >> 2, k0 = (s & 3) << 3;
            int tok = toks[row];
            float4 v0 = make_float4(0.f, 0.f, 0.f, 0.f), v1 = v0;
            if (tok >= 0) {
                const float4* p = (const float4*)(x + (size_t)tok * HDIM + h0 + k0);
                v0 = p[0]; v1 = p[1];
            }
            int off = row * STRD + k0;
            split8h(v0, v1, sXH + off, sXL + off);
        }
        // stage weights (single digit) from prefetched registers
        cvt8h(pg0, pg1, sGH + woff);
        cvt8h(pu0, pu1, sUH + woff);
        __syncthreads();

        // prefetch next chunk's weights (hidden behind MMAs)
        if (ch + 1 < NCH1) {
            int hn = (ch + 1) * KC;
            pg0 = *(const float4*)(gptr + hn);
            pg1 = *(const float4*)(gptr + hn + 4);
            pu0 = *(const float4*)(uptr + hn);
            pu1 = *(const float4*)(uptr + hn + 4);
        }

#pragma unroll
        for (int ks = 0; ks < 2; ks++) {
            int kb = ks * 16;
            uint32_t bgh[4], buh[4];
            ldsm4(bgh, lds_addr(bGH, nw, kb, lane));
            ldsm4(buh, lds_addr(bUH, nw, kb, lane));
#pragma unroll
            for (int mf = 0; mf < 4; mf++) {
                uint32_t ah[4], al[4];
                ldsm4(ah, lds_addr(bXH, mw + mf * 16, kb, lane));
                ldsm4(al, lds_addr(bXL, mw + mf * 16, kb, lane));
#pragma unroll
                for (int nf = 0; nf < 2; nf++) {
                    mmaf16(cg[mf][nf], ah, bgh[nf], bgh[nf + 2]);
                    mmaf16(cg[mf][nf], al, bgh[nf], bgh[nf + 2]);
                    mmaf16(cu[mf][nf], ah, buh[nf], buh[nf + 2]);
                    mmaf16(cu[mf][nf], al, buh[nf], buh[nf + 2]);
                }
            }
        }
        __syncthreads();
    }

    // epilogue: silu*mul, split, store hi/lo fp16 act
    __half* AH = (__half*)g_act_hi;
    __half* AL = (__half*)g_act_lo;
#pragma unroll
    for (int mf = 0; mf < 4; mf++) {
#pragma unroll
        for (int nf = 0; nf < 2; nf++) {
            int mg = row0 + mw + mf * 16 + (lane >> 2);
            int ng = i0 + nw + nf * 8 + ((lane & 3) << 1);
#pragma unroll
            for (int h = 0; h < 2; h++) {
                float a0 = silu_mul(cg[mf][nf][h * 2],     cu[mf][nf][h * 2]);
                float a1 = silu_mul(cg[mf][nf][h * 2 + 1], cu[mf][nf][h * 2 + 1]);
                __half h0 = __float2half(a0), h1 = __float2half(a1);
                __half l0 = __float2half(a0 - __half2float(h0));
                __half l1 = __float2half(a1 - __half2float(h1));
                size_t idx = (size_t)(mg + h * 8) * IDIM + ng;
                *(__half2*)(AH + idx) = __halves2half2(h0, h1);
                *(__half2*)(AL + idx) = __halves2half2(l0, l1);
            }
        }
    }
}

// ---------------- GEMM2: y = ew * (act . downT) ----------------
// act 2-digit fp16; down single-digit fp16.
__global__ __launch_bounds__(256, 2)
void gemm2_mma(const float* __restrict__ down,
               const float* __restrict__ ew) {
    int e = g_tile_expert[blockIdx.y];
    if (e < 0) return;
    int row0 = g_tile_row0[blockIdx.y];
    int hb = blockIdx.x * TN;

    __shared__ __align__(16) __half sAH[TM * STRD], sAL[TM * STRD];
    __shared__ __align__(16) __half sWH[TN * STRD];
    __shared__ int   slots[TM];
    __shared__ float swt[TM];

    int tid = threadIdx.x;
    int lane = tid & 31, wid = tid >> 5;
    int mw = (wid >> 2) * 64;
    int nw = (wid & 3) * 16;

    if (tid < TM) {
        int p = g_perm[row0 + tid];
        slots[tid] = p;
        swt[tid] = (p >= 0) ? ew[p] : 0.f;
    }
    __syncthreads();

    uint32_t bAH = smem_to_u32(sAH), bAL = smem_to_u32(sAL);
    uint32_t bWH = smem_to_u32(sWH);

    // fixed per-thread staging tasks
    int ar0 = tid >> 2, ak0 = tid & 3;
    int ar1 = (tid + 256) >> 2;
    const uint4* ahp0 = g_act_hi + (size_t)(row0 + ar0) * (IDIM / 8) + ak0;
    const uint4* alp0 = g_act_lo + (size_t)(row0 + ar0) * (IDIM / 8) + ak0;
    const uint4* ahp1 = g_act_hi + (size_t)(row0 + ar1) * (IDIM / 8) + ak0;
    const uint4* alp1 = g_act_lo + (size_t)(row0 + ar1) * (IDIM / 8) + ak0;
    int aoff0 = ar0 * STRD + (ak0 << 3);
    int aoff1 = ar1 * STRD + (ak0 << 3);
    int wr = tid >> 2, wk0 = (tid & 3) << 3;
    const float* wptr = down + ((size_t)e * HDIM + hb + wr) * IDIM + wk0;
    int woff = wr * STRD + wk0;

    float acc[4][2][4];
#pragma unroll
    for (int mf = 0; mf < 4; mf++)
#pragma unroll
        for (int nf = 0; nf < 2; nf++)
#pragma unroll
            for (int q = 0; q < 4; q++) acc[mf][nf][q] = 0.f;

    // prologue: prefetch chunk 0
    uint4 pa0h = ahp0[0], pa0l = alp0[0];
    uint4 pa1h = ahp1[0], pa1l = alp1[0];
    float4 pw0 = *(const float4*)(wptr);
    float4 pw1 = *(const float4*)(wptr + 4);

    for (int ch = 0; ch < NCH2; ch++) {
        *(uint4*)(sAH + aoff0) = pa0h;
        *(uint4*)(sAL + aoff0) = pa0l;
        *(uint4*)(sAH + aoff1) = pa1h;
        *(uint4*)(sAL + aoff1) = pa1l;
        cvt8h(pw0, pw1, sWH + woff);
        __syncthreads();

        if (ch + 1 < NCH2) {
            int kq = (ch + 1) * (KC / 8);
            int kn = (ch + 1) * KC;
            pa0h = ahp0[kq]; pa0l = alp0[kq];
            pa1h = ahp1[kq]; pa1l = alp1[kq];
            pw0 = *(const float4*)(wptr + kn);
            pw1 = *(const float4*)(wptr + kn + 4);
        }

#pragma unroll
        for (int ks = 0; ks < 2; ks++) {
            int kb = ks * 16;
            uint32_t bwh[4];
            ldsm4(bwh, lds_addr(bWH, nw, kb, lane));
#pragma unroll
            for (int mf = 0; mf < 4; mf++) {
                uint32_t ah[4], al[4];
                ldsm4(ah, lds_addr(bAH, mw + mf * 16, kb, lane));
                ldsm4(al, lds_addr(bAL, mw + mf * 16, kb, lane));
#pragma unroll
                for (int nf = 0; nf < 2; nf++) {
                    mmaf16(acc[mf][nf], ah, bwh[nf], bwh[nf + 2]);
                    mmaf16(acc[mf][nf], al, bwh[nf], bwh[nf + 2]);
                }
            }
        }
        __syncthreads();
    }

    // epilogue: scale by routing weight, scatter to per-slot y
#pragma unroll
    for (int mf = 0; mf < 4; mf++) {
#pragma unroll
        for (int nf = 0; nf < 2; nf++) {
            int ml = mw + mf * 16 + (lane >> 2);
            int ng = hb + nw + nf * 8 + ((lane & 3) << 1);
#pragma unroll
            for (int h = 0; h < 2; h++) {
                int m = ml + h * 8;
                int p = slots[m];
                if (p >= 0) {
                    float w = swt[m];
                    float2 o;
                    o.x = acc[mf][nf][h * 2] * w;
                    o.y = acc[mf][nf][h * 2 + 1] * w;
                    *(float2*)(g_y + (size_t)p * HDIM + ng) = o;
                }
            }
        }
    }
}

// ---------------- combine ----------------
__global__ void combine_kernel(float* __restrict__ out) {
    const int HQ = HDIM / 4;
    int i = blockIdx.x * blockDim.x + threadIdx.x;
    if (i >= NTOK * HQ) return;
    int t = i / HQ, hq = i - t * HQ;
    const float4* y4 = (const float4*)g_y;
    float4 a = y4[(size_t)(2 * t) * HQ + hq];
    float4 b = y4[(size_t)(2 * t + 1) * HQ + hq];
    float4 o;
    o.x = a.x + b.x; o.y = a.y + b.y; o.z = a.z + b.z; o.w = a.w + b.w;
    ((float4*)out)[(size_t)t * HQ + hq] = o;
}

extern "C" void kernel_launch(void* const* d_in, const int* in_sizes, int n_in,
                              void* d_out, int out_size) {
    const float* x    = (const float*)d_in[0];
    const int*   ei   = (const int*)d_in[1];
    const float* ew   = (const float*)d_in[2];
    const float* gate = (const float*)d_in[3];
    const float* up   = (const float*)d_in[4];
    const float* down = (const float*)d_in[5];
    float* out = (float*)d_out;

    route_kernel<<<1, 256>>>(ei);
    gemm1_mma<<<dim3(IDIM / TN, TILE_MAX), 256>>>(x, gate, up);
    gemm2_mma<<<dim3(HDIM / TN, TILE_MAX), 256>>>(down, ew);
    combine_kernel<<<(NTOK * (HDIM / 4) + 255) / 256, 256>>>(out);
}

// round 16
// speedup vs baseline: 2.6732x; 1.0612x over previous
#include <cuda_runtime.h>
#include <cuda_fp16.h>
#include <math.h>
#include <stdint.h>

// ---------------- problem constants ----------------
#define HDIM 1024
#define IDIM 4096
#define NEXP 8
#define NTOK 4096          // B*S
#define NSLOT 8192         // NTOK*TOPK
#define TM 128             // CTA M tile
#define TN 64              // CTA N tile
#define KC 32              // K elems per chunk
#define NCH1 (HDIM / KC)   // 32
#define NCH2 (IDIM / KC)   // 128
#define PAD_MAX 9216
#define TILE_MAX 72
#define STRD 40            // smem row stride in elems (32 + 8 pad) -> 80B rows

// ---------------- device scratch (static, no allocs) ----------------
__device__ int   g_perm[PAD_MAX];
__device__ int   g_tile_expert[TILE_MAX];
__device__ int   g_tile_row0[TILE_MAX];
// pre-converted operands (fp16), uint4-packed (8 halves per entry)
__device__ uint4 g_x16h[(size_t)NTOK * HDIM / 8];          // x hi digit
__device__ uint4 g_x16l[(size_t)NTOK * HDIM / 8];          // x lo digit
__device__ uint4 g_g16[(size_t)NEXP * IDIM * HDIM / 8];    // gate fp16
__device__ uint4 g_u16[(size_t)NEXP * IDIM * HDIM / 8];    // up fp16
__device__ uint4 g_d16[(size_t)NEXP * HDIM * IDIM / 8];    // down fp16
// act stored pre-split as fp16 hi/lo, row-major [PAD_MAX][IDIM]
__device__ uint4 g_act_hi[(size_t)PAD_MAX * IDIM / 8];
__device__ uint4 g_act_lo[(size_t)PAD_MAX * IDIM / 8];
__device__ float g_y[(size_t)NSLOT * HDIM];

// ---------------- helpers ----------------
__device__ __forceinline__ uint32_t smem_to_u32(const void* p) {
    uint32_t a;
    asm("{ .reg .u64 t; cvta.to.shared.u64 t, %1; cvt.u32.u64 %0, t; }" : "=r"(a) : "l"(p));
    return a;
}
__device__ __forceinline__ void ldsm4(uint32_t* r, uint32_t addr) {
    asm volatile("ldmatrix.sync.aligned.m8n8.x4.shared.b16 {%0,%1,%2,%3}, [%4];"
                 : "=r"(r[0]), "=r"(r[1]), "=r"(r[2]), "=r"(r[3]) : "r"(addr));
}
__device__ __forceinline__ void mmaf16(float* c, const uint32_t* a, uint32_t b0, uint32_t b1) {
    asm volatile(
        "mma.sync.aligned.m16n8k16.row.col.f32.f16.f16.f32 "
        "{%0,%1,%2,%3}, {%4,%5,%6,%7}, {%8,%9}, {%0,%1,%2,%3};"
        : "+f"(c[0]), "+f"(c[1]), "+f"(c[2]), "+f"(c[3])
        : "r"(a[0]), "r"(a[1]), "r"(a[2]), "r"(a[3]), "r"(b0), "r"(b1));
}
__device__ __forceinline__ uint32_t lds_addr(uint32_t base, int row, int k, int lane) {
    int r = row + (lane & 15);
    int kk = k + ((lane >> 4) << 3);
    return base + (uint32_t)(r * (STRD * 2) + kk * 2);
}
__device__ __forceinline__ float silu_mul(float g, float u) {
    return g * u / (1.0f + expf(-g));
}

// ---------------- pre-conversion kernels (dst chosen in device code) ----------------
// weights: fp32 -> fp16 single digit
__global__ __launch_bounds__(256)
void cvt_w16(const float4* __restrict__ src, int which, int n8) {
    int i = blockIdx.x * blockDim.x + threadIdx.x;
    if (i >= n8) return;
    uint4* dst = (which == 1) ? g_g16 : (which == 2) ? g_u16 : g_d16;
    float4 a = src[2 * i], b = src[2 * i + 1];
    union { __half h[8]; uint4 u; } H;
    H.h[0] = __float2half(a.x); H.h[1] = __float2half(a.y);
    H.h[2] = __float2half(a.z); H.h[3] = __float2half(a.w);
    H.h[4] = __float2half(b.x); H.h[5] = __float2half(b.y);
    H.h[6] = __float2half(b.z); H.h[7] = __float2half(b.w);
    dst[i] = H.u;
}
// x: fp32 -> fp16 hi + fp16 residual
__global__ __launch_bounds__(256)
void split_x16(const float4* __restrict__ src, int n8) {
    int i = blockIdx.x * blockDim.x + threadIdx.x;
    if (i >= n8) return;
    float4 a = src[2 * i], b = src[2 * i + 1];
    float f[8] = {a.x, a.y, a.z, a.w, b.x, b.y, b.z, b.w};
    union { __half h[8]; uint4 u; } H, L;
#pragma unroll
    for (int j = 0; j < 8; j++) {
        __half h = __float2half(f[j]);
        H.h[j] = h;
        L.h[j] = __float2half(f[j] - __half2float(h));
    }
    g_x16h[i] = H.u;
    g_x16l[i] = L.u;
}

// ---------------- routing (output-order invariant) ----------------
__global__ void route_kernel(const int* __restrict__ ei) {
    __shared__ int cnt[NEXP];
    __shared__ int cur[NEXP];
    int tid = threadIdx.x;
    if (tid < NEXP) cnt[tid] = 0;
    __syncthreads();
    for (int s = tid; s < NSLOT; s += blockDim.x) atomicAdd(&cnt[ei[s]], 1);
    __syncthreads();
    if (tid == 0) {
        int base = 0, tile = 0;
        for (int e = 0; e < NEXP; e++) {
            cur[e] = base;
            int nt = (cnt[e] + TM - 1) / TM;
            for (int j = 0; j < nt; j++) { g_tile_expert[tile] = e; g_tile_row0[tile] = base + j * TM; tile++; }
            base += nt * TM;
        }
        for (; tile < TILE_MAX; tile++) g_tile_expert[tile] = -1;
    }
    __syncthreads();
    for (int r = tid; r < PAD_MAX; r += blockDim.x) g_perm[r] = -1;
    __syncthreads();
    for (int s = tid; s < NSLOT; s += blockDim.x) {
        int e = ei[s];
        int pos = atomicAdd(&cur[e], 1);
        g_perm[pos] = s;
    }
}

// ---------------- GEMM1: act = silu(x.gateT) * (x.upT) ----------------
// All staging = prefetched uint4 copies (x hi/lo 2-digit, weights single-digit).
__global__ __launch_bounds__(256, 2)
void gemm1_mma() {
    int e = g_tile_expert[blockIdx.y];
    if (e < 0) return;
    int row0 = g_tile_row0[blockIdx.y];
    int i0 = blockIdx.x * TN;

    __shared__ __align__(16) __half sXH[TM * STRD], sXL[TM * STRD];
    __shared__ __align__(16) __half sGH[TN * STRD], sUH[TN * STRD];
    __shared__ int toks[TM];

    int tid = threadIdx.x;
    int lane = tid & 31, wid = tid >> 5;
    int mw = (wid >> 2) * 64;
    int nw = (wid & 3) * 16;

    if (tid < TM) {
        int p = g_perm[row0 + tid];
        toks[tid] = (p >= 0) ? (p >> 1) : -1;
    }
    __syncthreads();

    uint32_t bXH = smem_to_u32(sXH), bXL = smem_to_u32(sXL);
    uint32_t bGH = smem_to_u32(sGH), bUH = smem_to_u32(sUH);

    // fixed per-thread staging tasks (uint4 = 8 halves = 16B)
    int xr0 = tid >> 2, xq = tid & 3;
    int xr1 = xr0 + 64;
    int t0 = toks[xr0], t1 = toks[xr1];
    const uint4* xh0 = (t0 >= 0) ? (g_x16h + (size_t)t0 * (HDIM / 8) + xq) : (const uint4*)0;
    const uint4* xl0 = (t0 >= 0) ? (g_x16l + (size_t)t0 * (HDIM / 8) + xq) : (const uint4*)0;
    const uint4* xh1 = (t1 >= 0) ? (g_x16h + (size_t)t1 * (HDIM / 8) + xq) : (const uint4*)0;
    const uint4* xl1 = (t1 >= 0) ? (g_x16l + (size_t)t1 * (HDIM / 8) + xq) : (const uint4*)0;
    int xoff0 = xr0 * STRD + xq * 8;
    int xoff1 = xr1 * STRD + xq * 8;
    int wr = tid >> 2, wq = tid & 3;
    const uint4* wg = g_g16 + (size_t)(e * IDIM + i0 + wr) * (HDIM / 8) + wq;
    const uint4* wu = g_u16 + (size_t)(e * IDIM + i0 + wr) * (HDIM / 8) + wq;
    int woff = wr * STRD + wq * 8;

    float cg[4][2][4], cu[4][2][4];
#pragma unroll
    for (int mf = 0; mf < 4; mf++)
#pragma unroll
        for (int nf = 0; nf < 2; nf++)
#pragma unroll
            for (int q = 0; q < 4; q++) { cg[mf][nf][q] = 0.f; cu[mf][nf][q] = 0.f; }

    const uint4 Z = make_uint4(0, 0, 0, 0);
    // prologue: prefetch chunk 0
    uint4 ph0 = xh0 ? xh0[0] : Z, pl0 = xl0 ? xl0[0] : Z;
    uint4 ph1 = xh1 ? xh1[0] : Z, pl1 = xl1 ? xl1[0] : Z;
    uint4 pg = wg[0], pu = wu[0];

    for (int ch = 0; ch < NCH1; ch++) {
        *(uint4*)(sXH + xoff0) = ph0;
        *(uint4*)(sXL + xoff0) = pl0;
        *(uint4*)(sXH + xoff1) = ph1;
        *(uint4*)(sXL + xoff1) = pl1;
        *(uint4*)(sGH + woff) = pg;
        *(uint4*)(sUH + woff) = pu;
        __syncthreads();

        if (ch + 1 < NCH1) {
            int o = (ch + 1) * (KC / 8);
            ph0 = xh0 ? xh0[o] : Z; pl0 = xl0 ? xl0[o] : Z;
            ph1 = xh1 ? xh1[o] : Z; pl1 = xl1 ? xl1[o] : Z;
            pg = wg[o]; pu = wu[o];
        }

#pragma unroll
        for (int ks = 0; ks < 2; ks++) {
            int kb = ks * 16;
            uint32_t bgh[4], buh[4];
            ldsm4(bgh, lds_addr(bGH, nw, kb, lane));
            ldsm4(buh, lds_addr(bUH, nw, kb, lane));
#pragma unroll
            for (int mf = 0; mf < 4; mf++) {
                uint32_t ah[4], al[4];
                ldsm4(ah, lds_addr(bXH, mw + mf * 16, kb, lane));
                ldsm4(al, lds_addr(bXL, mw + mf * 16, kb, lane));
#pragma unroll
                for (int nf = 0; nf < 2; nf++) {
                    mmaf16(cg[mf][nf], ah, bgh[nf], bgh[nf + 2]);
                    mmaf16(cg[mf][nf], al, bgh[nf], bgh[nf + 2]);
                    mmaf16(cu[mf][nf], ah, buh[nf], buh[nf + 2]);
                    mmaf16(cu[mf][nf], al, buh[nf], buh[nf + 2]);
                }
            }
        }
        __syncthreads();
    }

    // epilogue: silu*mul, split, store hi/lo fp16 act
    __half* AH = (__half*)g_act_hi;
    __half* AL = (__half*)g_act_lo;
#pragma unroll
    for (int mf = 0; mf < 4; mf++) {
#pragma unroll
        for (int nf = 0; nf < 2; nf++) {
            int mg = row0 + mw + mf * 16 + (lane >> 2);
            int ng = i0 + nw + nf * 8 + ((lane & 3) << 1);
#pragma unroll
            for (int h = 0; h < 2; h++) {
                float a0 = silu_mul(cg[mf][nf][h * 2],     cu[mf][nf][h * 2]);
                float a1 = silu_mul(cg[mf][nf][h * 2 + 1], cu[mf][nf][h * 2 + 1]);
                __half h0 = __float2half(a0), h1 = __float2half(a1);
                __half l0 = __float2half(a0 - __half2float(h0));
                __half l1 = __float2half(a1 - __half2float(h1));
                size_t idx = (size_t)(mg + h * 8) * IDIM + ng;
                *(__half2*)(AH + idx) = __halves2half2(h0, h1);
                *(__half2*)(AL + idx) = __halves2half2(l0, l1);
            }
        }
    }
}

// ---------------- GEMM2: y = ew * (act . downT) ----------------
__global__ __launch_bounds__(256, 2)
void gemm2_mma(const float* __restrict__ ew) {
    int e = g_tile_expert[blockIdx.y];
    if (e < 0) return;
    int row0 = g_tile_row0[blockIdx.y];
    int hb = blockIdx.x * TN;

    __shared__ __align__(16) __half sAH[TM * STRD], sAL[TM * STRD];
    __shared__ __align__(16) __half sWH[TN * STRD];
    __shared__ int   slots[TM];
    __shared__ float swt[TM];

    int tid = threadIdx.x;
    int lane = tid & 31, wid = tid >> 5;
    int mw = (wid >> 2) * 64;
    int nw = (wid & 3) * 16;

    if (tid < TM) {
        int p = g_perm[row0 + tid];
        slots[tid] = p;
        swt[tid] = (p >= 0) ? ew[p] : 0.f;
    }
    __syncthreads();

    uint32_t bAH = smem_to_u32(sAH), bAL = smem_to_u32(sAL);
    uint32_t bWH = smem_to_u32(sWH);

    int ar0 = tid >> 2, aq = tid & 3;
    int ar1 = ar0 + 64;
    const uint4* ah0 = g_act_hi + (size_t)(row0 + ar0) * (IDIM / 8) + aq;
    const uint4* al0 = g_act_lo + (size_t)(row0 + ar0) * (IDIM / 8) + aq;
    const uint4* ah1 = g_act_hi + (size_t)(row0 + ar1) * (IDIM / 8) + aq;
    const uint4* al1 = g_act_lo + (size_t)(row0 + ar1) * (IDIM / 8) + aq;
    int aoff0 = ar0 * STRD + aq * 8;
    int aoff1 = ar1 * STRD + aq * 8;
    int wr = tid >> 2, wq = tid & 3;
    const uint4* wd = g_d16 + (size_t)(e * HDIM + hb + wr) * (IDIM / 8) + wq;
    int woff = wr * STRD + wq * 8;

    float acc[4][2][4];
#pragma unroll
    for (int mf = 0; mf < 4; mf++)
#pragma unroll
        for (int nf = 0; nf < 2; nf++)
#pragma unroll
            for (int q = 0; q < 4; q++) acc[mf][nf][q] = 0.f;

    // prologue: prefetch chunk 0
    uint4 ph0 = ah0[0], pl0 = al0[0];
    uint4 ph1 = ah1[0], pl1 = al1[0];
    uint4 pw = wd[0];

    for (int ch = 0; ch < NCH2; ch++) {
        *(uint4*)(sAH + aoff0) = ph0;
        *(uint4*)(sAL + aoff0) = pl0;
        *(uint4*)(sAH + aoff1) = ph1;
        *(uint4*)(sAL + aoff1) = pl1;
        *(uint4*)(sWH + woff) = pw;
        __syncthreads();

        if (ch + 1 < NCH2) {
            int o = (ch + 1) * (KC / 8);
            ph0 = ah0[o]; pl0 = al0[o];
            ph1 = ah1[o]; pl1 = al1[o];
            pw = wd[o];
        }

#pragma unroll
        for (int ks = 0; ks < 2; ks++) {
            int kb = ks * 16;
            uint32_t bwh[4];
            ldsm4(bwh, lds_addr(bWH, nw, kb, lane));
#pragma unroll
            for (int mf = 0; mf < 4; mf++) {
                uint32_t ah[4], al[4];
                ldsm4(ah, lds_addr(bAH, mw + mf * 16, kb, lane));
                ldsm4(al, lds_addr(bAL, mw + mf * 16, kb, lane));
#pragma unroll
                for (int nf = 0; nf < 2; nf++) {
                    mmaf16(acc[mf][nf], ah, bwh[nf], bwh[nf + 2]);
                    mmaf16(acc[mf][nf], al, bwh[nf], bwh[nf + 2]);
                }
            }
        }
        __syncthreads();
    }

    // epilogue: scale by routing weight, scatter to per-slot y
#pragma unroll
    for (int mf = 0; mf < 4; mf++) {
#pragma unroll
        for (int nf = 0; nf < 2; nf++) {
            int ml = mw + mf * 16 + (lane >> 2);
            int ng = hb + nw + nf * 8 + ((lane & 3) << 1);
#pragma unroll
            for (int h = 0; h < 2; h++) {
                int m = ml + h * 8;
                int p = slots[m];
                if (p >= 0) {
                    float w = swt[m];
                    float2 o;
                    o.x = acc[mf][nf][h * 2] * w;
                    o.y = acc[mf][nf][h * 2 + 1] * w;
                    *(float2*)(g_y + (size_t)p * HDIM + ng) = o;
                }
            }
        }
    }
}

// ---------------- combine ----------------
__global__ void combine_kernel(float* __restrict__ out) {
    const int HQ = HDIM / 4;
    int i = blockIdx.x * blockDim.x + threadIdx.x;
    if (i >= NTOK * HQ) return;
    int t = i / HQ, hq = i - t * HQ;
    const float4* y4 = (const float4*)g_y;
    float4 a = y4[(size_t)(2 * t) * HQ + hq];
    float4 b = y4[(size_t)(2 * t + 1) * HQ + hq];
    float4 o;
    o.x = a.x + b.x; o.y = a.y + b.y; o.z = a.z + b.z; o.w = a.w + b.w;
    ((float4*)out)[(size_t)t * HQ + hq] = o;
}

extern "C" void kernel_launch(void* const* d_in, const int* in_sizes, int n_in,
                              void* d_out, int out_size) {
    const float* x    = (const float*)d_in[0];
    const int*   ei   = (const int*)d_in[1];
    const float* ew   = (const float*)d_in[2];
    const float* gate = (const float*)d_in[3];
    const float* up   = (const float*)d_in[4];
    const float* down = (const float*)d_in[5];
    float* out = (float*)d_out;

    const int WN8 = (int)((size_t)NEXP * IDIM * HDIM / 8);   // 4194304
    const int XN8 = (int)((size_t)NTOK * HDIM / 8);          // 524288

    route_kernel<<<1, 256>>>(ei);
    split_x16<<<(XN8 + 255) / 256, 256>>>((const float4*)x, XN8);
    cvt_w16<<<(WN8 + 255) / 256, 256>>>((const float4*)gate, 1, WN8);
    cvt_w16<<<(WN8 + 255) / 256, 256>>>((const float4*)up,   2, WN8);
    cvt_w16<<<(WN8 + 255) / 256, 256>>>((const float4*)down, 3, WN8);

    gemm1_mma<<<dim3(IDIM / TN, TILE_MAX), 256>>>();
    gemm2_mma<<<dim3(HDIM / TN, TILE_MAX), 256>>>(ew);
    combine_kernel<<<(NTOK * (HDIM / 4) + 255) / 256, 256>>>(out);
}

// round 17
// speedup vs baseline: 3.1855x; 1.1916x over previous
#include <cuda_runtime.h>
#include <cuda_fp16.h>
#include <math.h>
#include <stdint.h>

// ---------------- problem constants ----------------
#define HDIM 1024
#define IDIM 4096
#define NEXP 8
#define NTOK 4096          // B*S
#define NSLOT 8192         // NTOK*TOPK
#define TM 128             // CTA M tile
#define TN 64              // CTA N tile
#define KC 32              // K elems per chunk
#define NCH1 (HDIM / KC)   // 32
#define NCH2 (IDIM / KC)   // 128
#define PAD_MAX 9216
#define TILE_MAX 72
#define STRD 40            // smem row stride in elems (32 + 8 pad) -> 80B rows

// ---------------- device scratch (static, no allocs) ----------------
__device__ int   g_perm[PAD_MAX];
__device__ int   g_tile_expert[TILE_MAX];
__device__ int   g_tile_row0[TILE_MAX];
// pre-converted operands (fp16), uint4-packed (8 halves per entry)
__device__ uint4 g_x16h[(size_t)NTOK * HDIM / 8];          // x hi digit
__device__ uint4 g_x16l[(size_t)NTOK * HDIM / 8];          // x lo digit
__device__ uint4 g_g16[(size_t)NEXP * IDIM * HDIM / 8];    // gate fp16
__device__ uint4 g_u16[(size_t)NEXP * IDIM * HDIM / 8];    // up fp16
__device__ uint4 g_d16[(size_t)NEXP * HDIM * IDIM / 8];    // down fp16
// act stored as single-digit fp16 (lo digit dropped — GEMM2 error budget)
__device__ uint4 g_act_hi[(size_t)PAD_MAX * IDIM / 8];
__device__ float g_y[(size_t)NSLOT * HDIM];

// ---------------- helpers ----------------
__device__ __forceinline__ uint32_t smem_to_u32(const void* p) {
    uint32_t a;
    asm("{ .reg .u64 t; cvta.to.shared.u64 t, %1; cvt.u32.u64 %0, t; }" : "=r"(a) : "l"(p));
    return a;
}
__device__ __forceinline__ void ldsm4(uint32_t* r, uint32_t addr) {
    asm volatile("ldmatrix.sync.aligned.m8n8.x4.shared.b16 {%0,%1,%2,%3}, [%4];"
                 : "=r"(r[0]), "=r"(r[1]), "=r"(r[2]), "=r"(r[3]) : "r"(addr));
}
__device__ __forceinline__ void mmaf16(float* c, const uint32_t* a, uint32_t b0, uint32_t b1) {
    asm volatile(
        "mma.sync.aligned.m16n8k16.row.col.f32.f16.f16.f32 "
        "{%0,%1,%2,%3}, {%4,%5,%6,%7}, {%8,%9}, {%0,%1,%2,%3};"
        : "+f"(c[0]), "+f"(c[1]), "+f"(c[2]), "+f"(c[3])
        : "r"(a[0]), "r"(a[1]), "r"(a[2]), "r"(a[3]), "r"(b0), "r"(b1));
}
__device__ __forceinline__ uint32_t lds_addr(uint32_t base, int row, int k, int lane) {
    int r = row + (lane & 15);
    int kk = k + ((lane >> 4) << 3);
    return base + (uint32_t)(r * (STRD * 2) + kk * 2);
}
__device__ __forceinline__ float silu_mul(float g, float u) {
    return g * u / (1.0f + expf(-g));
}

// ---------------- pre-conversion kernels (dst chosen in device code) ----------------
__global__ __launch_bounds__(256)
void cvt_w16(const float4* __restrict__ src, int which, int n8) {
    int i = blockIdx.x * blockDim.x + threadIdx.x;
    if (i >= n8) return;
    uint4* dst = (which == 1) ? g_g16 : (which == 2) ? g_u16 : g_d16;
    float4 a = src[2 * i], b = src[2 * i + 1];
    union { __half h[8]; uint4 u; } H;
    H.h[0] = __float2half(a.x); H.h[1] = __float2half(a.y);
    H.h[2] = __float2half(a.z); H.h[3] = __float2half(a.w);
    H.h[4] = __float2half(b.x); H.h[5] = __float2half(b.y);
    H.h[6] = __float2half(b.z); H.h[7] = __float2half(b.w);
    dst[i] = H.u;
}
__global__ __launch_bounds__(256)
void split_x16(const float4* __restrict__ src, int n8) {
    int i = blockIdx.x * blockDim.x + threadIdx.x;
    if (i >= n8) return;
    float4 a = src[2 * i], b = src[2 * i + 1];
    float f[8] = {a.x, a.y, a.z, a.w, b.x, b.y, b.z, b.w};
    union { __half h[8]; uint4 u; } H, L;
#pragma unroll
    for (int j = 0; j < 8; j++) {
        __half h = __float2half(f[j]);
        H.h[j] = h;
        L.h[j] = __float2half(f[j] - __half2float(h));
    }
    g_x16h[i] = H.u;
    g_x16l[i] = L.u;
}

// ---------------- routing (output-order invariant) ----------------
__global__ void route_kernel(const int* __restrict__ ei) {
    __shared__ int cnt[NEXP];
    __shared__ int cur[NEXP];
    int tid = threadIdx.x;
    if (tid < NEXP) cnt[tid] = 0;
    __syncthreads();
    for (int s = tid; s < NSLOT; s += blockDim.x) atomicAdd(&cnt[ei[s]], 1);
    __syncthreads();
    if (tid == 0) {
        int base = 0, tile = 0;
        for (int e = 0; e < NEXP; e++) {
            cur[e] = base;
            int nt = (cnt[e] + TM - 1) / TM;
            for (int j = 0; j < nt; j++) { g_tile_expert[tile] = e; g_tile_row0[tile] = base + j * TM; tile++; }
            base += nt * TM;
        }
        for (; tile < TILE_MAX; tile++) g_tile_expert[tile] = -1;
    }
    __syncthreads();
    for (int r = tid; r < PAD_MAX; r += blockDim.x) g_perm[r] = -1;
    __syncthreads();
    for (int s = tid; s < NSLOT; s += blockDim.x) {
        int e = ei[s];
        int pos = atomicAdd(&cur[e], 1);
        g_perm[pos] = s;
    }
}

// ---------------- GEMM1: act = silu(x.gateT) * (x.upT) ----------------
// x 2-digit fp16; weights single-digit; act stored single-digit fp16.
__global__ __launch_bounds__(256, 2)
void gemm1_mma() {
    int e = g_tile_expert[blockIdx.y];
    if (e < 0) return;
    int row0 = g_tile_row0[blockIdx.y];
    int i0 = blockIdx.x * TN;

    __shared__ __align__(16) __half sXH[TM * STRD], sXL[TM * STRD];
    __shared__ __align__(16) __half sGH[TN * STRD], sUH[TN * STRD];
    __shared__ int toks[TM];

    int tid = threadIdx.x;
    int lane = tid & 31, wid = tid >> 5;
    int mw = (wid >> 2) * 64;
    int nw = (wid & 3) * 16;

    if (tid < TM) {
        int p = g_perm[row0 + tid];
        toks[tid] = (p >= 0) ? (p >> 1) : -1;
    }
    __syncthreads();

    uint32_t bXH = smem_to_u32(sXH), bXL = smem_to_u32(sXL);
    uint32_t bGH = smem_to_u32(sGH), bUH = smem_to_u32(sUH);

    int xr0 = tid >> 2, xq = tid & 3;
    int xr1 = xr0 + 64;
    int t0 = toks[xr0], t1 = toks[xr1];
    const uint4* xh0 = (t0 >= 0) ? (g_x16h + (size_t)t0 * (HDIM / 8) + xq) : (const uint4*)0;
    const uint4* xl0 = (t0 >= 0) ? (g_x16l + (size_t)t0 * (HDIM / 8) + xq) : (const uint4*)0;
    const uint4* xh1 = (t1 >= 0) ? (g_x16h + (size_t)t1 * (HDIM / 8) + xq) : (const uint4*)0;
    const uint4* xl1 = (t1 >= 0) ? (g_x16l + (size_t)t1 * (HDIM / 8) + xq) : (const uint4*)0;
    int xoff0 = xr0 * STRD + xq * 8;
    int xoff1 = xr1 * STRD + xq * 8;
    int wr = tid >> 2, wq = tid & 3;
    const uint4* wg = g_g16 + (size_t)(e * IDIM + i0 + wr) * (HDIM / 8) + wq;
    const uint4* wu = g_u16 + (size_t)(e * IDIM + i0 + wr) * (HDIM / 8) + wq;
    int woff = wr * STRD + wq * 8;

    float cg[4][2][4], cu[4][2][4];
#pragma unroll
    for (int mf = 0; mf < 4; mf++)
#pragma unroll
        for (int nf = 0; nf < 2; nf++)
#pragma unroll
            for (int q = 0; q < 4; q++) { cg[mf][nf][q] = 0.f; cu[mf][nf][q] = 0.f; }

    const uint4 Z = make_uint4(0, 0, 0, 0);
    uint4 ph0 = xh0 ? xh0[0] : Z, pl0 = xl0 ? xl0[0] : Z;
    uint4 ph1 = xh1 ? xh1[0] : Z, pl1 = xl1 ? xl1[0] : Z;
    uint4 pg = wg[0], pu = wu[0];

    for (int ch = 0; ch < NCH1; ch++) {
        *(uint4*)(sXH + xoff0) = ph0;
        *(uint4*)(sXL + xoff0) = pl0;
        *(uint4*)(sXH + xoff1) = ph1;
        *(uint4*)(sXL + xoff1) = pl1;
        *(uint4*)(sGH + woff) = pg;
        *(uint4*)(sUH + woff) = pu;
        __syncthreads();

        if (ch + 1 < NCH1) {
            int o = (ch + 1) * (KC / 8);
            ph0 = xh0 ? xh0[o] : Z; pl0 = xl0 ? xl0[o] : Z;
            ph1 = xh1 ? xh1[o] : Z; pl1 = xl1 ? xl1[o] : Z;
            pg = wg[o]; pu = wu[o];
        }

#pragma unroll
        for (int ks = 0; ks < 2; ks++) {
            int kb = ks * 16;
            uint32_t bgh[4], buh[4];
            ldsm4(bgh, lds_addr(bGH, nw, kb, lane));
            ldsm4(buh, lds_addr(bUH, nw, kb, lane));
#pragma unroll
            for (int mf = 0; mf < 4; mf++) {
                uint32_t ah[4], al[4];
                ldsm4(ah, lds_addr(bXH, mw + mf * 16, kb, lane));
                ldsm4(al, lds_addr(bXL, mw + mf * 16, kb, lane));
#pragma unroll
                for (int nf = 0; nf < 2; nf++) {
                    mmaf16(cg[mf][nf], ah, bgh[nf], bgh[nf + 2]);
                    mmaf16(cg[mf][nf], al, bgh[nf], bgh[nf + 2]);
                    mmaf16(cu[mf][nf], ah, buh[nf], buh[nf + 2]);
                    mmaf16(cu[mf][nf], al, buh[nf], buh[nf + 2]);
                }
            }
        }
        __syncthreads();
    }

    // epilogue: silu*mul, store single-digit fp16 act
    __half* AH = (__half*)g_act_hi;
#pragma unroll
    for (int mf = 0; mf < 4; mf++) {
#pragma unroll
        for (int nf = 0; nf < 2; nf++) {
            int mg = row0 + mw + mf * 16 + (lane >> 2);
            int ng = i0 + nw + nf * 8 + ((lane & 3) << 1);
#pragma unroll
            for (int h = 0; h < 2; h++) {
                float a0 = silu_mul(cg[mf][nf][h * 2],     cu[mf][nf][h * 2]);
                float a1 = silu_mul(cg[mf][nf][h * 2 + 1], cu[mf][nf][h * 2 + 1]);
                size_t idx = (size_t)(mg + h * 8) * IDIM + ng;
                *(__half2*)(AH + idx) = __halves2half2(__float2half(a0), __float2half(a1));
            }
        }
    }
}

// ---------------- GEMM2: y = ew * (act . downT), single-digit both sides ----------------
__global__ __launch_bounds__(256, 2)
void gemm2_mma(const float* __restrict__ ew) {
    int e = g_tile_expert[blockIdx.y];
    if (e < 0) return;
    int row0 = g_tile_row0[blockIdx.y];
    int hb = blockIdx.x * TN;

    __shared__ __align__(16) __half sAH[TM * STRD];
    __shared__ __align__(16) __half sWH[TN * STRD];
    __shared__ int   slots[TM];
    __shared__ float swt[TM];

    int tid = threadIdx.x;
    int lane = tid & 31, wid = tid >> 5;
    int mw = (wid >> 2) * 64;
    int nw = (wid & 3) * 16;

    if (tid < TM) {
        int p = g_perm[row0 + tid];
        slots[tid] = p;
        swt[tid] = (p >= 0) ? ew[p] : 0.f;
    }
    __syncthreads();

    uint32_t bAH = smem_to_u32(sAH);
    uint32_t bWH = smem_to_u32(sWH);

    int ar0 = tid >> 2, aq = tid & 3;
    int ar1 = ar0 + 64;
    const uint4* ah0 = g_act_hi + (size_t)(row0 + ar0) * (IDIM / 8) + aq;
    const uint4* ah1 = g_act_hi + (size_t)(row0 + ar1) * (IDIM / 8) + aq;
    int aoff0 = ar0 * STRD + aq * 8;
    int aoff1 = ar1 * STRD + aq * 8;
    int wr = tid >> 2, wq = tid & 3;
    const uint4* wd = g_d16 + (size_t)(e * HDIM + hb + wr) * (IDIM / 8) + wq;
    int woff = wr * STRD + wq * 8;

    float acc[4][2][4];
#pragma unroll
    for (int mf = 0; mf < 4; mf++)
#pragma unroll
        for (int nf = 0; nf < 2; nf++)
#pragma unroll
            for (int q = 0; q < 4; q++) acc[mf][nf][q] = 0.f;

    uint4 ph0 = ah0[0], ph1 = ah1[0];
    uint4 pw = wd[0];

    for (int ch = 0; ch < NCH2; ch++) {
        *(uint4*)(sAH + aoff0) = ph0;
        *(uint4*)(sAH + aoff1) = ph1;
        *(uint4*)(sWH + woff) = pw;
        __syncthreads();

        if (ch + 1 < NCH2) {
            int o = (ch + 1) * (KC / 8);
            ph0 = ah0[o]; ph1 = ah1[o];
            pw = wd[o];
        }

#pragma unroll
        for (int ks = 0; ks < 2; ks++) {
            int kb = ks * 16;
            uint32_t bwh[4];
            ldsm4(bwh, lds_addr(bWH, nw, kb, lane));
#pragma unroll
            for (int mf = 0; mf < 4; mf++) {
                uint32_t ah[4];
                ldsm4(ah, lds_addr(bAH, mw + mf * 16, kb, lane));
#pragma unroll
                for (int nf = 0; nf < 2; nf++) {
                    mmaf16(acc[mf][nf], ah, bwh[nf], bwh[nf + 2]);
                }
            }
        }
        __syncthreads();
    }

    // epilogue: scale by routing weight, scatter to per-slot y
#pragma unroll
    for (int mf = 0; mf < 4; mf++) {
#pragma unroll
        for (int nf = 0; nf < 2; nf++) {
            int ml = mw + mf * 16 + (lane >> 2);
            int ng = hb + nw + nf * 8 + ((lane & 3) << 1);
#pragma unroll
            for (int h = 0; h < 2; h++) {
                int m = ml + h * 8;
                int p = slots[m];
                if (p >= 0) {
                    float w = swt[m];
                    float2 o;
                    o.x = acc[mf][nf][h * 2] * w;
                    o.y = acc[mf][nf][h * 2 + 1] * w;
                    *(float2*)(g_y + (size_t)p * HDIM + ng) = o;
                }
            }
        }
    }
}

// ---------------- combine ----------------
__global__ void combine_kernel(float* __restrict__ out) {
    const int HQ = HDIM / 4;
    int i = blockIdx.x * blockDim.x + threadIdx.x;
    if (i >= NTOK * HQ) return;
    int t = i / HQ, hq = i - t * HQ;
    const float4* y4 = (const float4*)g_y;
    float4 a = y4[(size_t)(2 * t) * HQ + hq];
    float4 b = y4[(size_t)(2 * t + 1) * HQ + hq];
    float4 o;
    o.x = a.x + b.x; o.y = a.y + b.y; o.z = a.z + b.z; o.w = a.w + b.w;
    ((float4*)out)[(size_t)t * HQ + hq] = o;
}

extern "C" void kernel_launch(void* const* d_in, const int* in_sizes, int n_in,
                              void* d_out, int out_size) {
    const float* x    = (const float*)d_in[0];
    const int*   ei   = (const int*)d_in[1];
    const float* ew   = (const float*)d_in[2];
    const float* gate = (const float*)d_in[3];
    const float* up   = (const float*)d_in[4];
    const float* down = (const float*)d_in[5];
    float* out = (float*)d_out;

    const int WN8 = (int)((size_t)NEXP * IDIM * HDIM / 8);   // 4194304
    const int XN8 = (int)((size_t)NTOK * HDIM / 8);          // 524288

    route_kernel<<<1, 256>>>(ei);
    split_x16<<<(XN8 + 255) / 256, 256>>>((const float4*)x, XN8);
    cvt_w16<<<(WN8 + 255) / 256, 256>>>((const float4*)gate, 1, WN8);
    cvt_w16<<<(WN8 + 255) / 256, 256>>>((const float4*)up,   2, WN8);
    cvt_w16<<<(WN8 + 255) / 256, 256>>>((const float4*)down, 3, WN8);

    gemm1_mma<<<dim3(IDIM / TN, TILE_MAX), 256>>>();
    gemm2_mma<<<dim3(HDIM / TN, TILE_MAX), 256>>>(ew);
    combine_kernel<<<(NTOK * (HDIM / 4) + 255) / 256, 256>>>(out);
}